// round 2
// baseline (speedup 1.0000x reference)
#include <cuda_runtime.h>
#include <cstdint>

// Problem constants
#define MM   32      // latent dim
#define BB   1000    // number of segments (T)
#define H1   512
#define H2   2048
#define DD   3072

// Padded scratch shapes (pad M-dims to tile multiples; pad rows are handled so
// they never contaminate the result).
#define X1_ROWS 2048   // rows 0..999 = h1, 1000..1999 = t1, 2000..2047 unused
#define T2_ROWS 1024   // rows 0..999 = t2, 1000..1023 zeroed
#define NPART   512

// Static device scratch (no allocation allowed in kernel_launch).
__device__ float g_X1[X1_ROWS * H1];       // 4 MB
__device__ float g_Y2[X1_ROWS * H2];       // 16 MB
__device__ float g_T2[T2_ROWS * H2];       // 8 MB
__device__ float g_U3[T2_ROWS * DD];       // 12 MB
__device__ float g_part[NPART];

// ---------------------------------------------------------------------------
// K1: layer-1 forward + tangent (elementwise over 32-dim contraction).
//   z_b  = c[b],  dc_b = c[b+1]-c[b]  with c = [c0, interior..., c1]
//   a1   = z@W1 + b1 ; g = dc@W1
//   X1[b]       = relu(a1)
//   X1[1000+b]  = (a1>0) ? g : 0
// ---------------------------------------------------------------------------
__global__ void k_layer1(const float* __restrict__ c0,
                         const float* __restrict__ c1,
                         const float* __restrict__ interior,
                         const float* __restrict__ W1,
                         const float* __restrict__ b1) {
    int b = blockIdx.x;            // 0..999
    __shared__ float zs[MM], ds[MM];
    if (threadIdx.x < MM) {
        int m = threadIdx.x;
        float zb = (b == 0)   ? c0[m] : interior[(b - 1) * MM + m];
        float cn = (b == BB-1) ? c1[m] : interior[b * MM + m];
        zs[m] = zb;
        ds[m] = cn - zb;
    }
    __syncthreads();
    for (int k = threadIdx.x; k < H1; k += blockDim.x) {
        float a = b1[k];
        float g = 0.0f;
        #pragma unroll
        for (int m = 0; m < MM; ++m) {
            float w = W1[m * H1 + k];
            a = fmaf(zs[m], w, a);
            g = fmaf(ds[m], w, g);
        }
        g_X1[b * H1 + k]        = fmaxf(a, 0.0f);
        g_X1[(BB + b) * H1 + k] = (a > 0.0f) ? g : 0.0f;
    }
}

// ---------------------------------------------------------------------------
// Generic fp32 SGEMM: C[M,N] = A[M,K] @ B[K,N], all row-major.
// BM=BN=128, BK=8, TM=TN=8, 256 threads. Requires M%128==0 is NOT needed
// (grid covers ceil; here all dims are exact multiples), K%8==0, N%128==0,
// 16B-aligned pointers.
// ---------------------------------------------------------------------------
__global__ void __launch_bounds__(256)
k_sgemm(const float* __restrict__ A, const float* __restrict__ B,
        float* __restrict__ C, int M, int N, int K) {
    __shared__ float As[8][128];
    __shared__ float Bs[8][128];

    const int bRow = blockIdx.y * 128;
    const int bCol = blockIdx.x * 128;
    const int tid  = threadIdx.x;

    const int aRow = tid >> 1;          // 0..127
    const int aCol = (tid & 1) * 4;     // 0 or 4
    const int bRowL = tid >> 5;         // 0..7
    const int bColL = (tid & 31) * 4;   // 0..124

    const int tRow = (tid >> 4) * 8;    // 0..120
    const int tCol = (tid & 15) * 8;    // 0..120

    float acc[8][8];
    #pragma unroll
    for (int i = 0; i < 8; ++i)
        #pragma unroll
        for (int j = 0; j < 8; ++j) acc[i][j] = 0.0f;

    const float* Ablk = A + (size_t)(bRow + aRow) * K + aCol;
    const float* Bblk = B + (size_t)bRowL * N + bCol + bColL;

    for (int k0 = 0; k0 < K; k0 += 8) {
        float4 av = *(const float4*)(Ablk + k0);
        As[aCol + 0][aRow] = av.x;
        As[aCol + 1][aRow] = av.y;
        As[aCol + 2][aRow] = av.z;
        As[aCol + 3][aRow] = av.w;
        float4 bv = *(const float4*)(Bblk + (size_t)k0 * N);
        *(float4*)&Bs[bRowL][bColL] = bv;
        __syncthreads();

        #pragma unroll
        for (int k = 0; k < 8; ++k) {
            float4 ra0 = *(const float4*)&As[k][tRow];
            float4 ra1 = *(const float4*)&As[k][tRow + 4];
            float4 rb0 = *(const float4*)&Bs[k][tCol];
            float4 rb1 = *(const float4*)&Bs[k][tCol + 4];
            float ra[8] = {ra0.x, ra0.y, ra0.z, ra0.w, ra1.x, ra1.y, ra1.z, ra1.w};
            float rb[8] = {rb0.x, rb0.y, rb0.z, rb0.w, rb1.x, rb1.y, rb1.z, rb1.w};
            #pragma unroll
            for (int i = 0; i < 8; ++i)
                #pragma unroll
                for (int j = 0; j < 8; ++j)
                    acc[i][j] = fmaf(ra[i], rb[j], acc[i][j]);
        }
        __syncthreads();
    }

    float* Cblk = C + (size_t)(bRow + tRow) * N + bCol + tCol;
    #pragma unroll
    for (int i = 0; i < 8; ++i) {
        float4 v0 = make_float4(acc[i][0], acc[i][1], acc[i][2], acc[i][3]);
        float4 v1 = make_float4(acc[i][4], acc[i][5], acc[i][6], acc[i][7]);
        *(float4*)(Cblk + (size_t)i * N)     = v0;
        *(float4*)(Cblk + (size_t)i * N + 4) = v1;
    }
}

// ---------------------------------------------------------------------------
// K3: layer-2 epilogue.  t2[b][j] = (Y2[b][j]+b2[j] > 0) ? Y2[1000+b][j] : 0
// Rows 1000..1023 of t2 are zeroed so the padded GEMM2 rows are exactly zero.
// ---------------------------------------------------------------------------
__global__ void k_relu_gate(const float* __restrict__ b2) {
    int idx = blockIdx.x * blockDim.x + threadIdx.x;   // over T2_ROWS*H2
    if (idx >= T2_ROWS * H2) return;
    int b = idx >> 11;       // /2048
    int j = idx & (H2 - 1);  // %2048
    float v = 0.0f;
    if (b < BB) {
        float a = g_Y2[b * H2 + j] + b2[j];
        if (a > 0.0f) v = g_Y2[(BB + b) * H2 + j];
    }
    g_T2[idx] = v;
}

// ---------------------------------------------------------------------------
// K5/K6: deterministic two-stage sum of squares of U3.
// ---------------------------------------------------------------------------
__global__ void k_sqsum_partial() {
    const int n4 = (T2_ROWS * DD) / 4;
    const float4* u = (const float4*)g_U3;
    float s = 0.0f;
    for (int i = blockIdx.x * blockDim.x + threadIdx.x; i < n4;
         i += gridDim.x * blockDim.x) {
        float4 v = u[i];
        s += v.x * v.x + v.y * v.y + v.z * v.z + v.w * v.w;
    }
    __shared__ float red[256];
    red[threadIdx.x] = s;
    __syncthreads();
    for (int o = 128; o > 0; o >>= 1) {
        if (threadIdx.x < o) red[threadIdx.x] += red[threadIdx.x + o];
        __syncthreads();
    }
    if (threadIdx.x == 0) g_part[blockIdx.x] = red[0];
}

__global__ void k_finalize(float* __restrict__ out) {
    __shared__ float red[256];
    float s = 0.0f;
    for (int i = threadIdx.x; i < NPART; i += 256) s += g_part[i];
    red[threadIdx.x] = s;
    __syncthreads();
    for (int o = 128; o > 0; o >>= 1) {
        if (threadIdx.x < o) red[threadIdx.x] += red[threadIdx.x + o];
        __syncthreads();
    }
    if (threadIdx.x == 0) out[0] = red[0];
}

// ---------------------------------------------------------------------------
// Launch
// Inputs: 0:c0 1:c1 2:interior 3:W1 4:b1 5:W2 6:b2 7:W3 8:b3 (b3 unused:
// bias drops out of the Jacobian).
// ---------------------------------------------------------------------------
extern "C" void kernel_launch(void* const* d_in, const int* in_sizes, int n_in,
                              void* d_out, int out_size) {
    const float* c0       = (const float*)d_in[0];
    const float* c1       = (const float*)d_in[1];
    const float* interior = (const float*)d_in[2];
    const float* W1       = (const float*)d_in[3];
    const float* b1       = (const float*)d_in[4];
    const float* W2       = (const float*)d_in[5];
    const float* b2       = (const float*)d_in[6];
    const float* W3       = (const float*)d_in[7];
    (void)in_sizes; (void)n_in; (void)out_size;

    float *X1p, *Y2p, *T2p, *U3p;
    cudaGetSymbolAddress((void**)&X1p, g_X1);
    cudaGetSymbolAddress((void**)&Y2p, g_Y2);
    cudaGetSymbolAddress((void**)&T2p, g_T2);
    cudaGetSymbolAddress((void**)&U3p, g_U3);

    // L1 forward + tangent
    k_layer1<<<BB, 256>>>(c0, c1, interior, W1, b1);

    // [h1;t1] @ W2  ->  Y2   (2048 x 2048, K=512)
    k_sgemm<<<dim3(H2 / 128, X1_ROWS / 128), 256>>>(X1p, W2, Y2p,
                                                    X1_ROWS, H2, H1);
    // gate: t2 = u2 * (a2 > 0)
    k_relu_gate<<<(T2_ROWS * H2 + 255) / 256, 256>>>(b2);

    // t2 @ W3 -> U3   (1024 x 3072, K=2048)
    k_sgemm<<<dim3(DD / 128, T2_ROWS / 128), 256>>>(T2p, W3, U3p,
                                                    T2_ROWS, DD, H2);

    // energy = sum(U3^2), deterministic two-stage reduction
    k_sqsum_partial<<<NPART, 256>>>();
    k_finalize<<<1, 256>>>((float*)d_out);
}

// round 3
// speedup vs baseline: 1.0029x; 1.0029x over previous
#include <cuda_runtime.h>
#include <cstdint>

// Problem constants
#define MM   32      // latent dim
#define BB   1000    // number of segments (T)
#define H1   512
#define H2   2048
#define DD   3072

// Padded scratch shapes (pad M-dims to tile multiples; pad rows are handled so
// they never contaminate the result).
#define X1_ROWS 2048   // rows 0..999 = h1, 1000..1999 = t1, 2000..2047 unused
#define T2_ROWS 1024   // rows 0..999 = t2, 1000..1023 zeroed
#define NPART   512

// Static device scratch (no allocation allowed in kernel_launch).
__device__ float g_X1[X1_ROWS * H1];       // 4 MB
__device__ float g_Y2[X1_ROWS * H2];       // 16 MB
__device__ float g_T2[T2_ROWS * H2];       // 8 MB
__device__ float g_U3[T2_ROWS * DD];       // 12 MB
__device__ float g_part[NPART];

// ---------------------------------------------------------------------------
// K1: layer-1 forward + tangent (elementwise over 32-dim contraction).
//   z_b  = c[b],  dc_b = c[b+1]-c[b]  with c = [c0, interior..., c1]
//   a1   = z@W1 + b1 ; g = dc@W1
//   X1[b]       = relu(a1)
//   X1[1000+b]  = (a1>0) ? g : 0
// ---------------------------------------------------------------------------
__global__ void k_layer1(const float* __restrict__ c0,
                         const float* __restrict__ c1,
                         const float* __restrict__ interior,
                         const float* __restrict__ W1,
                         const float* __restrict__ b1) {
    int b = blockIdx.x;            // 0..999
    __shared__ float zs[MM], ds[MM];
    if (threadIdx.x < MM) {
        int m = threadIdx.x;
        float zb = (b == 0)   ? c0[m] : interior[(b - 1) * MM + m];
        float cn = (b == BB-1) ? c1[m] : interior[b * MM + m];
        zs[m] = zb;
        ds[m] = cn - zb;
    }
    __syncthreads();
    for (int k = threadIdx.x; k < H1; k += blockDim.x) {
        float a = b1[k];
        float g = 0.0f;
        #pragma unroll
        for (int m = 0; m < MM; ++m) {
            float w = W1[m * H1 + k];
            a = fmaf(zs[m], w, a);
            g = fmaf(ds[m], w, g);
        }
        g_X1[b * H1 + k]        = fmaxf(a, 0.0f);
        g_X1[(BB + b) * H1 + k] = (a > 0.0f) ? g : 0.0f;
    }
}

// ---------------------------------------------------------------------------
// Generic fp32 SGEMM: C[M,N] = A[M,K] @ B[K,N], all row-major.
// BM=BN=128, BK=8, TM=TN=8, 256 threads. Requires M%128==0 is NOT needed
// (grid covers ceil; here all dims are exact multiples), K%8==0, N%128==0,
// 16B-aligned pointers.
// ---------------------------------------------------------------------------
__global__ void __launch_bounds__(256)
k_sgemm(const float* __restrict__ A, const float* __restrict__ B,
        float* __restrict__ C, int M, int N, int K) {
    __shared__ float As[8][128];
    __shared__ float Bs[8][128];

    const int bRow = blockIdx.y * 128;
    const int bCol = blockIdx.x * 128;
    const int tid  = threadIdx.x;

    const int aRow = tid >> 1;          // 0..127
    const int aCol = (tid & 1) * 4;     // 0 or 4
    const int bRowL = tid >> 5;         // 0..7
    const int bColL = (tid & 31) * 4;   // 0..124

    const int tRow = (tid >> 4) * 8;    // 0..120
    const int tCol = (tid & 15) * 8;    // 0..120

    float acc[8][8];
    #pragma unroll
    for (int i = 0; i < 8; ++i)
        #pragma unroll
        for (int j = 0; j < 8; ++j) acc[i][j] = 0.0f;

    const float* Ablk = A + (size_t)(bRow + aRow) * K + aCol;
    const float* Bblk = B + (size_t)bRowL * N + bCol + bColL;

    for (int k0 = 0; k0 < K; k0 += 8) {
        float4 av = *(const float4*)(Ablk + k0);
        As[aCol + 0][aRow] = av.x;
        As[aCol + 1][aRow] = av.y;
        As[aCol + 2][aRow] = av.z;
        As[aCol + 3][aRow] = av.w;
        float4 bv = *(const float4*)(Bblk + (size_t)k0 * N);
        *(float4*)&Bs[bRowL][bColL] = bv;
        __syncthreads();

        #pragma unroll
        for (int k = 0; k < 8; ++k) {
            float4 ra0 = *(const float4*)&As[k][tRow];
            float4 ra1 = *(const float4*)&As[k][tRow + 4];
            float4 rb0 = *(const float4*)&Bs[k][tCol];
            float4 rb1 = *(const float4*)&Bs[k][tCol + 4];
            float ra[8] = {ra0.x, ra0.y, ra0.z, ra0.w, ra1.x, ra1.y, ra1.z, ra1.w};
            float rb[8] = {rb0.x, rb0.y, rb0.z, rb0.w, rb1.x, rb1.y, rb1.z, rb1.w};
            #pragma unroll
            for (int i = 0; i < 8; ++i)
                #pragma unroll
                for (int j = 0; j < 8; ++j)
                    acc[i][j] = fmaf(ra[i], rb[j], acc[i][j]);
        }
        __syncthreads();
    }

    float* Cblk = C + (size_t)(bRow + tRow) * N + bCol + tCol;
    #pragma unroll
    for (int i = 0; i < 8; ++i) {
        float4 v0 = make_float4(acc[i][0], acc[i][1], acc[i][2], acc[i][3]);
        float4 v1 = make_float4(acc[i][4], acc[i][5], acc[i][6], acc[i][7]);
        *(float4*)(Cblk + (size_t)i * N)     = v0;
        *(float4*)(Cblk + (size_t)i * N + 4) = v1;
    }
}

// ---------------------------------------------------------------------------
// K3: layer-2 epilogue.  t2[b][j] = (Y2[b][j]+b2[j] > 0) ? Y2[1000+b][j] : 0
// Rows 1000..1023 of t2 are zeroed so the padded GEMM2 rows are exactly zero.
// ---------------------------------------------------------------------------
__global__ void k_relu_gate(const float* __restrict__ b2) {
    int idx = blockIdx.x * blockDim.x + threadIdx.x;   // over T2_ROWS*H2
    if (idx >= T2_ROWS * H2) return;
    int b = idx >> 11;       // /2048
    int j = idx & (H2 - 1);  // %2048
    float v = 0.0f;
    if (b < BB) {
        float a = g_Y2[b * H2 + j] + b2[j];
        if (a > 0.0f) v = g_Y2[(BB + b) * H2 + j];
    }
    g_T2[idx] = v;
}

// ---------------------------------------------------------------------------
// K5/K6: deterministic two-stage sum of squares of U3.
// ---------------------------------------------------------------------------
__global__ void k_sqsum_partial() {
    const int n4 = (T2_ROWS * DD) / 4;
    const float4* u = (const float4*)g_U3;
    float s = 0.0f;
    for (int i = blockIdx.x * blockDim.x + threadIdx.x; i < n4;
         i += gridDim.x * blockDim.x) {
        float4 v = u[i];
        s += v.x * v.x + v.y * v.y + v.z * v.z + v.w * v.w;
    }
    __shared__ float red[256];
    red[threadIdx.x] = s;
    __syncthreads();
    for (int o = 128; o > 0; o >>= 1) {
        if (threadIdx.x < o) red[threadIdx.x] += red[threadIdx.x + o];
        __syncthreads();
    }
    if (threadIdx.x == 0) g_part[blockIdx.x] = red[0];
}

__global__ void k_finalize(float* __restrict__ out) {
    __shared__ float red[256];
    float s = 0.0f;
    for (int i = threadIdx.x; i < NPART; i += 256) s += g_part[i];
    red[threadIdx.x] = s;
    __syncthreads();
    for (int o = 128; o > 0; o >>= 1) {
        if (threadIdx.x < o) red[threadIdx.x] += red[threadIdx.x + o];
        __syncthreads();
    }
    if (threadIdx.x == 0) out[0] = red[0];
}

// ---------------------------------------------------------------------------
// Launch
// Inputs: 0:c0 1:c1 2:interior 3:W1 4:b1 5:W2 6:b2 7:W3 8:b3 (b3 unused:
// bias drops out of the Jacobian).
// ---------------------------------------------------------------------------
extern "C" void kernel_launch(void* const* d_in, const int* in_sizes, int n_in,
                              void* d_out, int out_size) {
    const float* c0       = (const float*)d_in[0];
    const float* c1       = (const float*)d_in[1];
    const float* interior = (const float*)d_in[2];
    const float* W1       = (const float*)d_in[3];
    const float* b1       = (const float*)d_in[4];
    const float* W2       = (const float*)d_in[5];
    const float* b2       = (const float*)d_in[6];
    const float* W3       = (const float*)d_in[7];
    (void)in_sizes; (void)n_in; (void)out_size;

    float *X1p, *Y2p, *T2p, *U3p;
    cudaGetSymbolAddress((void**)&X1p, g_X1);
    cudaGetSymbolAddress((void**)&Y2p, g_Y2);
    cudaGetSymbolAddress((void**)&T2p, g_T2);
    cudaGetSymbolAddress((void**)&U3p, g_U3);

    // L1 forward + tangent
    k_layer1<<<BB, 256>>>(c0, c1, interior, W1, b1);

    // [h1;t1] @ W2  ->  Y2   (2048 x 2048, K=512)
    k_sgemm<<<dim3(H2 / 128, X1_ROWS / 128), 256>>>(X1p, W2, Y2p,
                                                    X1_ROWS, H2, H1);
    // gate: t2 = u2 * (a2 > 0)
    k_relu_gate<<<(T2_ROWS * H2 + 255) / 256, 256>>>(b2);

    // t2 @ W3 -> U3   (1024 x 3072, K=2048)
    k_sgemm<<<dim3(DD / 128, T2_ROWS / 128), 256>>>(T2p, W3, U3p,
                                                    T2_ROWS, DD, H2);

    // energy = sum(U3^2), deterministic two-stage reduction
    k_sqsum_partial<<<NPART, 256>>>();
    k_finalize<<<1, 256>>>((float*)d_out);
}